// round 1
// baseline (speedup 1.0000x reference)
#include <cuda_runtime.h>

// GPTQ int4 dequant GEMM: out[32, 8192] = x[32, 8192] @ dequant(W)[8192, 8192]^T + bias
// M=32, K=8192, N=8192, group=64.
// Strategy: FFMA2 (fma.rn.f32x2) CUDA-core kernel, K-split with atomicAdd epilogue.
// Dequant without I2F: f = 1 + q/16 built by OR-ing nibble into fp32 mantissa,
// w = A*f + B with A = 16*s, B = -s*(z+16)  (== s*q - s*z).

#define MM 32
#define KDIM 8192
#define NDIM 8192
#define GS 64
#define NGROUPS 128        // KDIM / GS
#define NTHREADS 256
#define NT 4               // n per thread
#define NBLK 512           // 128 n-threads * NT
#define KSPLIT 32
#define KPER 256           // KDIM / KSPLIT
#define GROUPS_PER 4       // KPER / GS
#define WS_ROW 36          // int32 per weight smem row (32 + pad, 16B-aligned rows)
#define XS_ROW 36          // floats per x smem row (32 + pad, 16B-aligned rows)

__device__ __forceinline__ unsigned long long ffma2(unsigned long long a,
                                                    unsigned long long b,
                                                    unsigned long long c) {
    unsigned long long d;
    asm("fma.rn.f32x2 %0, %1, %2, %3;" : "=l"(d) : "l"(a), "l"(b), "l"(c));
    return d;
}
__device__ __forceinline__ unsigned long long pack2(float lo, float hi) {
    unsigned long long d;
    asm("mov.b64 %0, {%1, %2};" : "=l"(d) : "f"(lo), "f"(hi));
    return d;
}
__device__ __forceinline__ void unpack2(unsigned long long v, float& lo, float& hi) {
    asm("mov.b64 {%0, %1}, %2;" : "=f"(lo), "=f"(hi) : "l"(v));
}

__global__ void __launch_bounds__(NTHREADS)
gptq_init(const float* __restrict__ bias, float* __restrict__ out) {
    int i = blockIdx.x * NTHREADS + threadIdx.x;   // grid sized exactly M*N/256
    out[i] = bias[i & (NDIM - 1)];
}

extern __shared__ char smem_raw[];

__global__ void __launch_bounds__(NTHREADS)
gptq_main(const float* __restrict__ x, const int* __restrict__ pw,
          const float* __restrict__ scales, const float* __restrict__ zeros,
          float* __restrict__ out)
{
    int*   ws = reinterpret_cast<int*>(smem_raw);                       // [NBLK][WS_ROW]
    float* xs = reinterpret_cast<float*>(smem_raw) + NBLK * WS_ROW;     // [GS][XS_ROW]

    const int tid = threadIdx.x;
    const int nt  = tid & 127;           // n-thread id 0..127
    const int m0  = (tid >> 7) * 16;     // m half: 0 or 16
    const int nblock0 = blockIdx.x * NBLK;
    const int k0 = blockIdx.y * KPER;
    const int g0 = k0 / GS;

    // accumulators: NT n's x 8 f32x2 pairs (16 m values)
    unsigned long long acc[NT][8];
#pragma unroll
    for (int j = 0; j < NT; ++j)
#pragma unroll
        for (int p = 0; p < 8; ++p) acc[j][p] = 0ull;

    for (int g = 0; g < GROUPS_PER; ++g) {
        const int kg = k0 + g * GS;
        __syncthreads();   // protect previous iteration's smem reads

        // ---- stage weights: NBLK rows x 32 int32 (8 int4 per row), coalesced ----
        const int* gsrc = pw + (kg >> 1);
#pragma unroll
        for (int i = 0; i < 16; ++i) {
            int lin = tid + i * NTHREADS;          // 0..4095
            int w4 = lin & 7;                      // int4 index within row
            int nl = lin >> 3;                     // local n row 0..511
            int4 v = *reinterpret_cast<const int4*>(
                gsrc + (size_t)(nblock0 + nl) * (KDIM / 2) + w4 * 4);
            *reinterpret_cast<int4*>(ws + nl * WS_ROW + w4 * 4) = v;
        }
        // ---- stage x: 64 k x 32 m, transposed to [kk][m] ----
#pragma unroll
        for (int i = 0; i < 8; ++i) {
            int lin = tid + i * NTHREADS;          // 0..2047
            int kk = lin & 63;
            int m  = lin >> 6;
            xs[kk * XS_ROW + m] = x[(size_t)m * KDIM + kg + kk];
        }
        __syncthreads();

        // per-(n, group) dequant constants
        float A[NT], B[NT];
#pragma unroll
        for (int j = 0; j < NT; ++j) {
            int n = nblock0 + nt + 128 * j;
            float s = __ldg(scales + (size_t)n * NGROUPS + g0 + g);
            float z = __ldg(zeros  + (size_t)n * NGROUPS + g0 + g);
            A[j] = 16.0f * s;
            B[j] = -s * (z + 16.0f);
        }

        // ---- main loop: 8 int4-steps x 8 k each ----
#pragma unroll 2
        for (int w4 = 0; w4 < 8; ++w4) {
            int4 wq[NT];
#pragma unroll
            for (int j = 0; j < NT; ++j)
                wq[j] = *reinterpret_cast<const int4*>(
                    ws + (nt + 128 * j) * WS_ROW + w4 * 4);

#pragma unroll
            for (int t = 0; t < 4; ++t) {
#pragma unroll
                for (int e = 0; e < 2; ++e) {
                    const int kk = w4 * 8 + t * 2 + e;
                    // x for this k: 16 m values as 8 packed f32x2 (broadcast LDS.128)
                    const ulonglong2* xr =
                        reinterpret_cast<const ulonglong2*>(xs + kk * XS_ROW + m0);
                    ulonglong2 p0 = xr[0];
                    ulonglong2 p1 = xr[1];
                    ulonglong2 p2 = xr[2];
                    ulonglong2 p3 = xr[3];
#pragma unroll
                    for (int j = 0; j < NT; ++j) {
                        int b = (t == 0) ? wq[j].x
                              : (t == 1) ? wq[j].y
                              : (t == 2) ? wq[j].z : wq[j].w;
                        // f = 1 + q/16 exactly: nibble into mantissa bits [19:23)
                        unsigned int fb =
                            (((unsigned int)b << (e ? 15 : 19)) & 0x00780000u) | 0x3F800000u;
                        float wv = fmaf(A[j], __uint_as_float(fb), B[j]);   // = s*q - s*z
                        unsigned long long w2 = pack2(wv, wv);
                        acc[j][0] = ffma2(p0.x, w2, acc[j][0]);
                        acc[j][1] = ffma2(p0.y, w2, acc[j][1]);
                        acc[j][2] = ffma2(p1.x, w2, acc[j][2]);
                        acc[j][3] = ffma2(p1.y, w2, acc[j][3]);
                        acc[j][4] = ffma2(p2.x, w2, acc[j][4]);
                        acc[j][5] = ffma2(p2.y, w2, acc[j][5]);
                        acc[j][6] = ffma2(p3.x, w2, acc[j][6]);
                        acc[j][7] = ffma2(p3.y, w2, acc[j][7]);
                    }
                }
            }
        }
    }

    // ---- epilogue: K-split partial sums via atomicAdd (coalesced over n) ----
#pragma unroll
    for (int j = 0; j < NT; ++j) {
        const int n = nblock0 + nt + 128 * j;
#pragma unroll
        for (int p = 0; p < 8; ++p) {
            float lo, hi;
            unpack2(acc[j][p], lo, hi);
            atomicAdd(out + (size_t)(m0 + 2 * p)     * NDIM + n, lo);
            atomicAdd(out + (size_t)(m0 + 2 * p + 1) * NDIM + n, hi);
        }
    }
}

extern "C" void kernel_launch(void* const* d_in, const int* in_sizes, int n_in,
                              void* d_out, int out_size) {
    const float* x      = (const float*)d_in[0];
    const int*   pw     = (const int*)d_in[1];
    const float* scales = (const float*)d_in[2];
    const float* zeros  = (const float*)d_in[3];
    const float* bias   = (const float*)d_in[4];
    float* out = (float*)d_out;

    // init out = bias (also un-poisons the buffer before atomics)
    gptq_init<<<(MM * NDIM) / NTHREADS, NTHREADS>>>(bias, out);

    size_t smem = (size_t)NBLK * WS_ROW * sizeof(int) + (size_t)GS * XS_ROW * sizeof(float);
    cudaFuncSetAttribute(gptq_main, cudaFuncAttributeMaxDynamicSharedMemorySize, (int)smem);

    dim3 grid(NDIM / NBLK, KSPLIT);
    gptq_main<<<grid, NTHREADS, smem>>>(x, pw, scales, zeros, out);
}

// round 2
// speedup vs baseline: 1.0162x; 1.0162x over previous
#include <cuda_runtime.h>

// GPTQ int4 dequant GEMM: out[32, 8192] = x[32, 8192] @ dequant(W)[8192,8192]^T + bias
// M=32, K=8192, N=8192, group=64.
// v2: FFMA2 core, weights via direct LDG.128 with register double-buffer prefetch
// (no weight smem, no mainloop barriers), x staged once, 2 CTAs/SM.

#define MM 32
#define KDIM 8192
#define NDIM 8192
#define GS 64
#define NGROUPS 128        // KDIM / GS
#define NTHREADS 256
#define NT 2               // n per thread
#define NBLK 256           // 128 n-threads * NT
#define KSPLIT 32
#define KPER 256           // KDIM / KSPLIT
#define GROUPS_PER 4       // KPER / GS
#define XS_ROW 36          // floats per x smem row (32 + pad, keeps 16B alignment)

__device__ __forceinline__ unsigned long long ffma2(unsigned long long a,
                                                    unsigned long long b,
                                                    unsigned long long c) {
    unsigned long long d;
    asm("fma.rn.f32x2 %0, %1, %2, %3;" : "=l"(d) : "l"(a), "l"(b), "l"(c));
    return d;
}
__device__ __forceinline__ unsigned long long pack2(float lo, float hi) {
    unsigned long long d;
    asm("mov.b64 %0, {%1, %2};" : "=l"(d) : "f"(lo), "f"(hi));
    return d;
}
__device__ __forceinline__ void unpack2(unsigned long long v, float& lo, float& hi) {
    asm("mov.b64 {%0, %1}, %2;" : "=f"(lo), "=f"(hi) : "l"(v));
}

__global__ void __launch_bounds__(NTHREADS)
gptq_init(const float* __restrict__ bias, float* __restrict__ out) {
    int i = blockIdx.x * NTHREADS + threadIdx.x;   // grid sized exactly M*N/256
    out[i] = bias[i & (NDIM - 1)];
}

__global__ void __launch_bounds__(NTHREADS, 2)
gptq_main(const float* __restrict__ x, const int* __restrict__ pw,
          const float* __restrict__ scales, const float* __restrict__ zeros,
          float* __restrict__ out)
{
    __shared__ float xs[KPER * XS_ROW];   // [k][m], 36864 B

    const int tid = threadIdx.x;
    const int nt  = tid & 127;            // n-thread id 0..127
    const int m0  = (tid >> 7) * 16;      // m half: 0 or 16
    const int nblock0 = blockIdx.x * NBLK;
    const int k0 = blockIdx.y * KPER;
    const int g0 = k0 / GS;

    // ---- stage x once: [KPER][32m] transposed into smem ----
#pragma unroll
    for (int i = 0; i < 8; ++i) {
        int lin = tid + i * NTHREADS;       // 0..2047 float4s
        int v = lin & 63;                   // float4 index along k (64 per m-row)
        int m = lin >> 6;                   // 0..31
        float4 xv = *reinterpret_cast<const float4*>(x + (size_t)m * KDIM + k0 + 4 * v);
        xs[(4 * v + 0) * XS_ROW + m] = xv.x;
        xs[(4 * v + 1) * XS_ROW + m] = xv.y;
        xs[(4 * v + 2) * XS_ROW + m] = xv.z;
        xs[(4 * v + 3) * XS_ROW + m] = xv.w;
    }

    // ---- dequant constants for all 4 groups, all NT rows ----
    float A[GROUPS_PER][NT], B[GROUPS_PER][NT];
#pragma unroll
    for (int j = 0; j < NT; ++j) {
        const int n = nblock0 + nt + 128 * j;
#pragma unroll
        for (int g = 0; g < GROUPS_PER; ++g) {
            float s = __ldg(scales + (size_t)n * NGROUPS + g0 + g);
            float z = __ldg(zeros  + (size_t)n * NGROUPS + g0 + g);
            A[g][j] = 16.0f * s;
            B[g][j] = -s * (z + 16.0f);
        }
    }

    // weight row pointers (int32 units); each step consumes one int4 = 16B = 8 k
    const int* wrow[NT];
#pragma unroll
    for (int j = 0; j < NT; ++j)
        wrow[j] = pw + (size_t)(nblock0 + nt + 128 * j) * (KDIM / 2) + (k0 >> 1);

    __syncthreads();

    unsigned long long acc[NT][8];
#pragma unroll
    for (int j = 0; j < NT; ++j)
#pragma unroll
        for (int p = 0; p < 8; ++p) acc[j][p] = 0ull;

    // prologue: load step 0
    int4 wq[NT];
#pragma unroll
    for (int j = 0; j < NT; ++j)
        wq[j] = *reinterpret_cast<const int4*>(wrow[j]);

#pragma unroll
    for (int g = 0; g < GROUPS_PER; ++g) {
#pragma unroll 1
        for (int w4 = 0; w4 < 8; ++w4) {
            // prefetch next step's weights (register double buffer)
            const int step = g * 8 + w4;
            int4 wqn[NT];
            if (step < GROUPS_PER * 8 - 1) {
#pragma unroll
                for (int j = 0; j < NT; ++j)
                    wqn[j] = *reinterpret_cast<const int4*>(wrow[j] + (step + 1) * 4);
            }

#pragma unroll
            for (int t = 0; t < 4; ++t) {
#pragma unroll
                for (int e = 0; e < 2; ++e) {
                    const int kk = g * GS + w4 * 8 + t * 2 + e;
                    const ulonglong2* xr =
                        reinterpret_cast<const ulonglong2*>(xs + kk * XS_ROW + m0);
                    ulonglong2 p0 = xr[0];
                    ulonglong2 p1 = xr[1];
                    ulonglong2 p2 = xr[2];
                    ulonglong2 p3 = xr[3];
#pragma unroll
                    for (int j = 0; j < NT; ++j) {
                        int b = (t == 0) ? wq[j].x
                              : (t == 1) ? wq[j].y
                              : (t == 2) ? wq[j].z : wq[j].w;
                        // f = 1 + q/16 exactly: nibble into mantissa bits [19:23)
                        unsigned int fb =
                            (((unsigned int)b << (e ? 15 : 19)) & 0x00780000u) | 0x3F800000u;
                        float wv = fmaf(A[g][j], __uint_as_float(fb), B[g][j]); // s*q - s*z
                        unsigned long long w2 = pack2(wv, wv);
                        acc[j][0] = ffma2(p0.x, w2, acc[j][0]);
                        acc[j][1] = ffma2(p0.y, w2, acc[j][1]);
                        acc[j][2] = ffma2(p1.x, w2, acc[j][2]);
                        acc[j][3] = ffma2(p1.y, w2, acc[j][3]);
                        acc[j][4] = ffma2(p2.x, w2, acc[j][4]);
                        acc[j][5] = ffma2(p2.y, w2, acc[j][5]);
                        acc[j][6] = ffma2(p3.x, w2, acc[j][6]);
                        acc[j][7] = ffma2(p3.y, w2, acc[j][7]);
                    }
                }
            }
#pragma unroll
            for (int j = 0; j < NT; ++j) wq[j] = wqn[j];
        }
    }

    // ---- epilogue: K-split partial sums via atomicAdd (coalesced over n) ----
#pragma unroll
    for (int j = 0; j < NT; ++j) {
        const int n = nblock0 + nt + 128 * j;
#pragma unroll
        for (int p = 0; p < 8; ++p) {
            float lo, hi;
            unpack2(acc[j][p], lo, hi);
            atomicAdd(out + (size_t)(m0 + 2 * p)     * NDIM + n, lo);
            atomicAdd(out + (size_t)(m0 + 2 * p + 1) * NDIM + n, hi);
        }
    }
}

extern "C" void kernel_launch(void* const* d_in, const int* in_sizes, int n_in,
                              void* d_out, int out_size) {
    const float* x      = (const float*)d_in[0];
    const int*   pw     = (const int*)d_in[1];
    const float* scales = (const float*)d_in[2];
    const float* zeros  = (const float*)d_in[3];
    const float* bias   = (const float*)d_in[4];
    float* out = (float*)d_out;

    // init out = bias (also un-poisons the buffer before atomics)
    gptq_init<<<(MM * NDIM) / NTHREADS, NTHREADS>>>(bias, out);

    dim3 grid(NDIM / NBLK, KSPLIT);
    gptq_main<<<grid, NTHREADS>>>(x, pw, scales, zeros, out);
}

// round 4
// speedup vs baseline: 1.1319x; 1.1139x over previous
#include <cuda_runtime.h>

// GPTQ int4 dequant GEMM: out[32, 8192] = x[32, 8192] @ dequant(W)[8192,8192]^T + bias
// M=32, K=8192, N=8192, group=64. One packed int32 = one byte = 2 k-nibbles.
// v4: FFMA2 core. Weights per-GROUP staged into a 2-deep smem ring via cp.async
// (coalesced LDG side, conflict-free 144B-stride LDS side). x staged once.
// K-split with fp32 atomicAdd epilogue.

#define MM 32
#define KDIM 8192
#define NDIM 8192
#define GS 64
#define NGROUPS 128        // KDIM / GS
#define NTHREADS 256
#define NT 2               // n per thread
#define NBLK 256           // 128 n-threads * NT
#define KSPLIT 32
#define KPER 256           // KDIM / KSPLIT
#define GROUPS_PER 4       // KPER / GS
#define WS_ROW 36          // int32 per weight smem row (32 data + 4 pad = 144B)
#define WS_BUF (NBLK * WS_ROW)   // int32 per weight buffer (one group)
#define XS_ROW 36          // floats per x smem row

__device__ __forceinline__ unsigned long long ffma2(unsigned long long a,
                                                    unsigned long long b,
                                                    unsigned long long c) {
    unsigned long long d;
    asm("fma.rn.f32x2 %0, %1, %2, %3;" : "=l"(d) : "l"(a), "l"(b), "l"(c));
    return d;
}
__device__ __forceinline__ unsigned long long pack2(float lo, float hi) {
    unsigned long long d;
    asm("mov.b64 %0, {%1, %2};" : "=l"(d) : "f"(lo), "f"(hi));
    return d;
}
__device__ __forceinline__ void unpack2(unsigned long long v, float& lo, float& hi) {
    asm("mov.b64 {%0, %1}, %2;" : "=f"(lo), "=f"(hi) : "l"(v));
}
__device__ __forceinline__ unsigned int smem_u32(const void* p) {
    unsigned int a;
    asm("{ .reg .u64 t; cvta.to.shared.u64 t, %1; cvt.u32.u64 %0, t; }"
        : "=r"(a) : "l"(p));
    return a;
}
__device__ __forceinline__ void cp_async16(unsigned int saddr, const void* gptr) {
    asm volatile("cp.async.cg.shared.global [%0], [%1], 16;\n"
                 :: "r"(saddr), "l"(gptr));
}
__device__ __forceinline__ void cp_commit() {
    asm volatile("cp.async.commit_group;\n" ::: "memory");
}
template <int N>
__device__ __forceinline__ void cp_wait() {
    asm volatile("cp.async.wait_group %0;\n" :: "n"(N) : "memory");
}

__global__ void __launch_bounds__(NTHREADS)
gptq_init(const float* __restrict__ bias, float* __restrict__ out) {
    int i = blockIdx.x * NTHREADS + threadIdx.x;   // grid sized exactly M*N/256
    out[i] = bias[i & (NDIM - 1)];
}

extern __shared__ char smem_raw[];

__global__ void __launch_bounds__(NTHREADS, 2)
gptq_main(const float* __restrict__ x, const int* __restrict__ pw,
          const float* __restrict__ scales, const float* __restrict__ zeros,
          float* __restrict__ out)
{
    int*   ws = reinterpret_cast<int*>(smem_raw);                     // [2][NBLK][WS_ROW]
    float* xs = reinterpret_cast<float*>(smem_raw) + 2 * WS_BUF;      // [KPER][XS_ROW]

    const int tid = threadIdx.x;
    const int nt  = tid & 127;            // n-thread id 0..127
    const int m0  = (tid >> 7) * 16;      // m half: 0 or 16
    const int nblock0 = blockIdx.x * NBLK;
    const int k0 = blockIdx.y * KPER;
    const int g0 = k0 / GS;

    const unsigned int ws_base = smem_u32(ws);

    // per-thread staging coords: 2048 16B chunks per group / 256 threads = 8 each
    const int s_chunk = tid & 7;          // 16B chunk within the row's group slice
    const int s_row0  = tid >> 3;         // rows s_row0, s_row0+32, ... (+224)

    // ---- issue cp.async for one group into buffer b ----
    auto stage_w = [&](int g, int b) {
        const int* gsrc = pw + ((k0 + g * GS) >> 1) + s_chunk * 4;
        unsigned int sdst = ws_base +
            (unsigned int)(b * WS_BUF + s_row0 * WS_ROW + s_chunk * 4) * 4u;
#pragma unroll
        for (int i = 0; i < 8; ++i) {
            cp_async16(sdst + (unsigned int)(i * 32 * WS_ROW) * 4u,
                       gsrc + (size_t)(nblock0 + s_row0 + i * 32) * (KDIM / 2));
        }
        cp_commit();
    };

    stage_w(0, 0);
    stage_w(1, 1);

    // ---- stage x once: [KPER][32m] transposed (overlaps with cp.async) ----
#pragma unroll
    for (int i = 0; i < 8; ++i) {
        int lin = tid + i * NTHREADS;       // 0..2047 float4s
        int v = lin & 63;                   // float4 index along k
        int m = lin >> 6;                   // 0..31
        float4 xv = *reinterpret_cast<const float4*>(x + (size_t)m * KDIM + k0 + 4 * v);
        xs[(4 * v + 0) * XS_ROW + m] = xv.x;
        xs[(4 * v + 1) * XS_ROW + m] = xv.y;
        xs[(4 * v + 2) * XS_ROW + m] = xv.z;
        xs[(4 * v + 3) * XS_ROW + m] = xv.w;
    }

    // ---- dequant constants for all 4 groups, both rows ----
    float A[GROUPS_PER][NT], B[GROUPS_PER][NT];
#pragma unroll
    for (int j = 0; j < NT; ++j) {
        const int n = nblock0 + nt + 128 * j;
#pragma unroll
        for (int g = 0; g < GROUPS_PER; ++g) {
            float s = __ldg(scales + (size_t)n * NGROUPS + g0 + g);
            float z = __ldg(zeros  + (size_t)n * NGROUPS + g0 + g);
            A[g][j] = 16.0f * s;
            B[g][j] = -s * (z + 16.0f);
        }
    }

    unsigned long long acc[NT][8];
#pragma unroll
    for (int j = 0; j < NT; ++j)
#pragma unroll
        for (int p = 0; p < 8; ++p) acc[j][p] = 0ull;

#pragma unroll
    for (int g = 0; g < GROUPS_PER; ++g) {
        if (g == GROUPS_PER - 1) cp_wait<0>(); else cp_wait<1>();
        __syncthreads();

        const int* wb = ws + (g & 1) * WS_BUF;
        const int4* wrow0 = reinterpret_cast<const int4*>(wb + (nt +   0) * WS_ROW);
        const int4* wrow1 = reinterpret_cast<const int4*>(wb + (nt + 128) * WS_ROW);

        int4 wq[NT];
        wq[0] = wrow0[0];
        wq[1] = wrow1[0];

#pragma unroll
        for (int w4 = 0; w4 < 8; ++w4) {
            int4 wqn[NT];
            if (w4 < 7) { wqn[0] = wrow0[w4 + 1]; wqn[1] = wrow1[w4 + 1]; }

#pragma unroll
            for (int t = 0; t < 4; ++t) {
#pragma unroll
                for (int e = 0; e < 2; ++e) {
                    const int kk = g * GS + w4 * 8 + t * 2 + e;
                    const ulonglong2* xr =
                        reinterpret_cast<const ulonglong2*>(xs + kk * XS_ROW + m0);
                    ulonglong2 p0 = xr[0];
                    ulonglong2 p1 = xr[1];
                    ulonglong2 p2 = xr[2];
                    ulonglong2 p3 = xr[3];
#pragma unroll
                    for (int j = 0; j < NT; ++j) {
                        int b = (t == 0) ? wq[j].x
                              : (t == 1) ? wq[j].y
                              : (t == 2) ? wq[j].z : wq[j].w;
                        // f = 1 + q/16 exactly: nibble into mantissa bits [19:23)
                        unsigned int fb =
                            (((unsigned int)b << (e ? 15 : 19)) & 0x00780000u) | 0x3F800000u;
                        float wv = fmaf(A[g][j], __uint_as_float(fb), B[g][j]); // s*q - s*z
                        unsigned long long w2 = pack2(wv, wv);
                        acc[j][0] = ffma2(p0.x, w2, acc[j][0]);
                        acc[j][1] = ffma2(p0.y, w2, acc[j][1]);
                        acc[j][2] = ffma2(p1.x, w2, acc[j][2]);
                        acc[j][3] = ffma2(p1.y, w2, acc[j][3]);
                        acc[j][4] = ffma2(p2.x, w2, acc[j][4]);
                        acc[j][5] = ffma2(p2.y, w2, acc[j][5]);
                        acc[j][6] = ffma2(p3.x, w2, acc[j][6]);
                        acc[j][7] = ffma2(p3.y, w2, acc[j][7]);
                    }
                }
            }
            wq[0] = wqn[0];
            wq[1] = wqn[1];
        }

        if (g < GROUPS_PER - 2) {
            __syncthreads();               // everyone done reading buf (g&1)
            stage_w(g + 2, g & 1);
        }
    }

    // ---- epilogue: K-split partial sums via atomicAdd (coalesced over n) ----
#pragma unroll
    for (int j = 0; j < NT; ++j) {
        const int n = nblock0 + nt + 128 * j;
#pragma unroll
        for (int p = 0; p < 8; ++p) {
            float lo, hi;
            unpack2(acc[j][p], lo, hi);
            atomicAdd(out + (size_t)(m0 + 2 * p)     * NDIM + n, lo);
            atomicAdd(out + (size_t)(m0 + 2 * p + 1) * NDIM + n, hi);
        }
    }
}

extern "C" void kernel_launch(void* const* d_in, const int* in_sizes, int n_in,
                              void* d_out, int out_size) {
    const float* x      = (const float*)d_in[0];
    const int*   pw     = (const int*)d_in[1];
    const float* scales = (const float*)d_in[2];
    const float* zeros  = (const float*)d_in[3];
    const float* bias   = (const float*)d_in[4];
    float* out = (float*)d_out;

    // init out = bias (also un-poisons the buffer before atomics)
    gptq_init<<<(MM * NDIM) / NTHREADS, NTHREADS>>>(bias, out);

    size_t smem = (size_t)2 * WS_BUF * sizeof(int) + (size_t)KPER * XS_ROW * sizeof(float);
    cudaFuncSetAttribute(gptq_main, cudaFuncAttributeMaxDynamicSharedMemorySize, (int)smem);

    dim3 grid(NDIM / NBLK, KSPLIT);
    gptq_main<<<grid, NTHREADS, smem>>>(x, pw, scales, zeros, out);
}

// round 5
// speedup vs baseline: 3.4525x; 3.0502x over previous
#include <cuda_runtime.h>
#include <cuda_fp16.h>

// GPTQ int4 dequant GEMM via HMMA: out[32,8192] = x @ dequant(W)^T + bias
// M=32, K=8192, N=8192, group=64. packed int32 = one byte = 2 k-nibbles.
// v5: mma.sync.m16n8k16 (fp16 in, f32 accum). Weights dequantized fp32->fp16
// straight from packed smem into B fragments. x converted to fp16 in smem,
// A frags via ldmatrix. cp.async per-group ring. K-split + atomicAdd epilogue.

#define MM 32
#define KDIM 8192
#define NDIM 8192
#define GS 64
#define NGROUPS 128
#define NTHREADS 256
#define NBLK 128           // n per CTA
#define KSPLIT 16
#define KPER 512           // k per CTA
#define GROUPS_PER 8       // KPER / GS
#define WROW 36            // int32 per ws row (32 data + 4 pad = 144B stride)
#define WBUF (NBLK * WROW) // int32 per ring buffer (one group)
#define WS_BYTES (2 * WBUF * 4)
#define XROWH 520          // halfs per xs row (512 + 8 pad = 1040B stride)

__device__ __forceinline__ unsigned smem_u32(const void* p) {
    unsigned a;
    asm("{ .reg .u64 t; cvta.to.shared.u64 t, %1; cvt.u32.u64 %0, t; }"
        : "=r"(a) : "l"(p));
    return a;
}
__device__ __forceinline__ void cp_async16(unsigned saddr, const void* gptr) {
    asm volatile("cp.async.cg.shared.global [%0], [%1], 16;\n"
                 :: "r"(saddr), "l"(gptr));
}
__device__ __forceinline__ void cp_commit() {
    asm volatile("cp.async.commit_group;\n" ::: "memory");
}
template <int N>
__device__ __forceinline__ void cp_wait() {
    asm volatile("cp.async.wait_group %0;\n" :: "n"(N) : "memory");
}
__device__ __forceinline__ void ldsm4(unsigned& r0, unsigned& r1,
                                      unsigned& r2, unsigned& r3, unsigned a) {
    asm volatile("ldmatrix.sync.aligned.m8n8.x4.shared.b16 {%0,%1,%2,%3}, [%4];"
                 : "=r"(r0), "=r"(r1), "=r"(r2), "=r"(r3) : "r"(a));
}
__device__ __forceinline__ void mma16816(float d[4], const unsigned a[4],
                                         const unsigned b[2]) {
    asm volatile(
        "mma.sync.aligned.m16n8k16.row.col.f32.f16.f16.f32 "
        "{%0,%1,%2,%3}, {%4,%5,%6,%7}, {%8,%9}, {%0,%1,%2,%3};"
        : "+f"(d[0]), "+f"(d[1]), "+f"(d[2]), "+f"(d[3])
        : "r"(a[0]), "r"(a[1]), "r"(a[2]), "r"(a[3]), "r"(b[0]), "r"(b[1]));
}
// dequant one packed byte (2 nibbles) -> fp16x2 {lo=even k, hi=odd k}
// f = 1 + q/16 exactly via mantissa OR; w = A*f + B = s*q - s*z (fp32), round once.
__device__ __forceinline__ unsigned dq2(int b, float Ag, float Bg) {
    unsigned flo = 0x3F800000u | (((unsigned)b << 19) & 0x00780000u);
    unsigned fhi = 0x3F800000u | (((unsigned)b << 15) & 0x00780000u);
    float wl = fmaf(Ag, __uint_as_float(flo), Bg);
    float wh = fmaf(Ag, __uint_as_float(fhi), Bg);
    unsigned r;
    asm("cvt.rn.f16x2.f32 %0, %2, %1;" : "=r"(r) : "f"(wl), "f"(wh)); // hi=wh, lo=wl
    return r;
}

__global__ void __launch_bounds__(NTHREADS)
gptq_init(const float* __restrict__ bias, float* __restrict__ out) {
    int i = blockIdx.x * NTHREADS + threadIdx.x;
    out[i] = bias[i & (NDIM - 1)];
}

extern __shared__ char smem_raw[];

__global__ void __launch_bounds__(NTHREADS, 2)
gptq_main(const float* __restrict__ x, const int* __restrict__ pw,
          const float* __restrict__ scales, const float* __restrict__ zeros,
          float* __restrict__ out)
{
    int* ws = reinterpret_cast<int*>(smem_raw);                      // [2][128][WROW]
    __half* xs = reinterpret_cast<__half*>(smem_raw + WS_BYTES);     // [32][XROWH]

    const int tid = threadIdx.x;
    const int w = tid >> 5;
    const int l = tid & 31;
    const int nblock0 = blockIdx.x * NBLK;
    const int k0 = blockIdx.y * KPER;
    const int g0 = blockIdx.y * GROUPS_PER;

    const unsigned ws_base = smem_u32(ws);
    const int s_chunk = tid & 7;        // 16B chunk within row's group slice (8*16B=32 int32)
    const int s_row0  = tid >> 3;       // rows s_row0 + 32*i, i<4

    auto stage_w = [&](int g, int b) {
        const int* gsrc = pw + ((k0 + g * GS) >> 1) + s_chunk * 4;
        unsigned sdst = ws_base + (unsigned)(b * WBUF + s_row0 * WROW + s_chunk * 4) * 4u;
#pragma unroll
        for (int i = 0; i < 4; ++i)
            cp_async16(sdst + (unsigned)(i * 32 * WROW) * 4u,
                       gsrc + (size_t)(nblock0 + s_row0 + i * 32) * (KDIM / 2));
        cp_commit();
    };
    stage_w(0, 0);
    stage_w(1, 1);

    // ---- stage x: [32 m][KPER k] fp32 -> fp16 in smem (row stride 1040B) ----
    {
        unsigned* xsu = reinterpret_cast<unsigned*>(xs);
#pragma unroll
        for (int i = 0; i < 16; ++i) {
            int lin = tid + i * NTHREADS;  // 0..4095 float4s
            int v = lin & 127;
            int m = lin >> 7;
            float4 xv = *reinterpret_cast<const float4*>(x + (size_t)m * KDIM + k0 + 4 * v);
            __half2 h0 = __floats2half2_rn(xv.x, xv.y);
            __half2 h1 = __floats2half2_rn(xv.z, xv.w);
            int idx = m * (XROWH / 2) + v * 2;
            xsu[idx]     = *reinterpret_cast<unsigned*>(&h0);
            xsu[idx + 1] = *reinterpret_cast<unsigned*>(&h1);
        }
    }

    // ---- dequant constants per (n-tile, group) ----
    float AA[2][GROUPS_PER], BB[2][GROUPS_PER];
#pragma unroll
    for (int t = 0; t < 2; ++t) {
        const int n = nblock0 + w * 16 + t * 8 + (l >> 2);
#pragma unroll
        for (int g = 0; g < GROUPS_PER; ++g) {
            float s = __ldg(scales + (size_t)n * NGROUPS + g0 + g);
            float z = __ldg(zeros  + (size_t)n * NGROUPS + g0 + g);
            AA[t][g] = 16.0f * s;
            BB[t][g] = -s * (z + 16.0f);
        }
    }

    // A-fragment ldmatrix lane addresses (x4: lanes 0-7 m0-7/k0, 8-15 m8-15/k0,
    // 16-23 m0-7/k8, 24-31 m8-15/k8)
    const unsigned xs_base = smem_u32(xs);
    const unsigned xa0 = xs_base + (unsigned)((l & 15) * XROWH * 2) + (unsigned)((l >> 4) * 16);
    const unsigned xa1 = xa0 + 16u * XROWH * 2;

    // weight smem indices: per tile, lane reads int32 (k-pair) (l&3) and (l&3)+4
    const int wr0 = (w * 16 + 0 + (l >> 2)) * WROW + (l & 3);
    const int wr1 = (w * 16 + 8 + (l >> 2)) * WROW + (l & 3);

    float acc[2][2][4] = {};   // [m-tile][n-tile][frag]

#pragma unroll
    for (int g = 0; g < GROUPS_PER; ++g) {
        if (g == GROUPS_PER - 1) cp_wait<0>(); else cp_wait<1>();
        __syncthreads();
        const int bufo = (g & 1) * WBUF;

#pragma unroll
        for (int s4 = 0; s4 < 4; ++s4) {
            const int s = g * 4 + s4;          // global k16-step 0..31
            unsigned a0[4], a1[4];
            ldsm4(a0[0], a0[1], a0[2], a0[3], xa0 + s * 32);
            ldsm4(a1[0], a1[1], a1[2], a1[3], xa1 + s * 32);

            const int q00 = ws[bufo + wr0 + s4 * 8];
            const int q01 = ws[bufo + wr0 + s4 * 8 + 4];
            const int q10 = ws[bufo + wr1 + s4 * 8];
            const int q11 = ws[bufo + wr1 + s4 * 8 + 4];

            unsigned b0[2], b1[2];
            b0[0] = dq2(q00, AA[0][g], BB[0][g]);
            b0[1] = dq2(q01, AA[0][g], BB[0][g]);
            b1[0] = dq2(q10, AA[1][g], BB[1][g]);
            b1[1] = dq2(q11, AA[1][g], BB[1][g]);

            mma16816(acc[0][0], a0, b0);
            mma16816(acc[0][1], a0, b1);
            mma16816(acc[1][0], a1, b0);
            mma16816(acc[1][1], a1, b1);
        }
        if (g < GROUPS_PER - 2) {
            __syncthreads();
            stage_w(g + 2, g & 1);
        }
    }

    // ---- epilogue: K-split partials via atomicAdd ----
#pragma unroll
    for (int tm = 0; tm < 2; ++tm) {
#pragma unroll
        for (int tn = 0; tn < 2; ++tn) {
            const int n = nblock0 + w * 16 + tn * 8 + (l & 3) * 2;
            const int m = tm * 16 + (l >> 2);
            float* o0 = out + (size_t)m * NDIM + n;
            atomicAdd(o0,     acc[tm][tn][0]);
            atomicAdd(o0 + 1, acc[tm][tn][1]);
            float* o1 = out + (size_t)(m + 8) * NDIM + n;
            atomicAdd(o1,     acc[tm][tn][2]);
            atomicAdd(o1 + 1, acc[tm][tn][3]);
        }
    }
}

extern "C" void kernel_launch(void* const* d_in, const int* in_sizes, int n_in,
                              void* d_out, int out_size) {
    const float* x      = (const float*)d_in[0];
    const int*   pw     = (const int*)d_in[1];
    const float* scales = (const float*)d_in[2];
    const float* zeros  = (const float*)d_in[3];
    const float* bias   = (const float*)d_in[4];
    float* out = (float*)d_out;

    gptq_init<<<(MM * NDIM) / NTHREADS, NTHREADS>>>(bias, out);

    size_t smem = WS_BYTES + (size_t)MM * XROWH * sizeof(__half);  // 36864 + 33280
    cudaFuncSetAttribute(gptq_main, cudaFuncAttributeMaxDynamicSharedMemorySize, (int)smem);

    dim3 grid(NDIM / NBLK, KSPLIT);
    gptq_main<<<grid, NTHREADS, smem>>>(x, pw, scales, zeros, out);
}